// round 8
// baseline (speedup 1.0000x reference)
#include <cuda_runtime.h>
#include <math.h>

// ---------------- Problem constants ----------------
#define WE 300
#define TE 10
#define SL 24
#define NT1 6
#define UT 3
#define H_LSTM 75          // WE/4
#define H_GRU 77           // (WE+TE)/4
#define CLS 27
#define D_IN 7210          // SL*WE + TE
#define BATCH 256
#define NSEQ 4608          // LSTM scan length
#define LSTM_B 24          // independent LSTM sequences
#define G4 300             // 4*H_LSTM
#define G3 231             // 3*H_GRU
#define CTXF 310           // WE+TE

// GEMM tiling
#define BM 128
#define BN 160
#define BK 20
#define NKT 15             // 300 / 20, exact
#define MCHUNKS 864        // 110592 / 128
#define NBLK_GEMM 1728     // MCHUNKS * 2

// LSTM X-prefetch depth (register ring, unrolled)
#define PF 8               // 4608 % 8 == 0

// ---------------- Scratch ----------------
__device__ float g_X[(long)NSEQ * LSTM_B * G4];     // ~132.7 MB
__device__ float g_H[(long)NSEQ * LSTM_B * H_LSTM]; // only t%18>=12 written
__device__ float g_ctx[BATCH * CTXF];
__device__ float g_XG[BATCH * G3];
__device__ float g_seqlast[BATCH * H_GRU];
__device__ int   g_flag[MCHUNKS];                   // per-M-chunk done count (target 2)

// ---------------- f32x2 packed helpers ----------------
__device__ __forceinline__ unsigned long long pack2(float lo, float hi) {
    unsigned long long r;
    asm("mov.b64 %0, {%1, %2};" : "=l"(r) : "f"(lo), "f"(hi));
    return r;
}
__device__ __forceinline__ float2 unpack2(unsigned long long v) {
    float2 f;
    asm("mov.b64 {%0, %1}, %2;" : "=f"(f.x), "=f"(f.y) : "l"(v));
    return f;
}
#define FMA2(d, a, b, c) \
    asm("fma.rn.f32x2 %0, %1, %2, %3;" : "=l"(d) : "l"(a), "l"(b), "l"(c))
#define ADD2(d, a, b) \
    asm("add.rn.f32x2 %0, %1, %2;" : "=l"(d) : "l"(a), "l"(b))

// ---------------- Activation helpers ----------------
__device__ __forceinline__ float sigmoidf_(float x) {
    return 1.0f / (1.0f + __expf(-x));
}
__device__ __forceinline__ float tanhf_(float x) {
    float e = __expf(-2.0f * fabsf(x));
    float t = (1.0f - e) / (1.0f + e);
    return copysignf(t, x);
}

// ---------------- Flag reset (runs before fused kernel each replay) ------
__global__ void init_flags_kernel() {
    if (threadIdx.x < MCHUNKS) g_flag[threadIdx.x] = 0;
}

// ---------------- Shared-memory overlays ----------------
struct GemmSmem {
    unsigned long long Bs2[BK][BN];   // B dup'd {b,b}: 25600 B
    float As[BK][BM];                 // A transposed [k][m]: 10240 B
};
struct LstmSmem {
    float h[80];
    float act[G4];
};

// =====================================================================
// FUSED kernel: blocks 0..23 = LSTM consumers, blocks 24.. = GEMM
// producers. LSTM keeps an 8-deep register pipeline of g_X loads so
// DRAM/L2 latency (~600-1000cyc) is fully covered (~8 steps of cover).
// =====================================================================
__global__ __launch_bounds__(320, 1) void fused_kernel(
    const float* __restrict__ A,      // inputs
    const float* __restrict__ W,      // lstm_W 300x300
    const float* __restrict__ bias,   // lstm_b 300
    const float* __restrict__ U)      // lstm_U 75x300
{
    __shared__ __align__(16) char smbuf[sizeof(GemmSmem)];
    const int tid = threadIdx.x;

    if (blockIdx.x >= LSTM_B) {
        // ================= GEMM producer =================
        GemmSmem& G = *reinterpret_cast<GemmSmem*>(smbuf);
        const int g = blockIdx.x - LSTM_B;
        const int mchunk = g >> 1;
        const int row0 = mchunk * BM;
        const int col0 = (g & 1) * BN;    // 0 or 160
        const int tr = tid / 20;          // 0..15 -> 8 M rows (4 pairs)
        const int tc = tid % 20;          // 0..19 -> 8 N cols

        // A-loader: 128 rows x 10 float2 = 1280 = 4/thread
        long abase[4]; int acol[4]; int arow_s[4];
#pragma unroll
        for (int i = 0; i < 4; i++) {
            int idx = tid + i * 320;
            arow_s[i] = idx / 10;
            int r = row0 + arow_s[i];
            abase[i] = (long)r * 300 + (r / 24) * 10;  // = s*7210 + m*300
            acol[i]  = (idx % 10) * 2;
        }
        // B-loader: 20 x 80 float2 = 1600 = 5/thread
        int bkk[5], bnn[5];
#pragma unroll
        for (int i = 0; i < 5; i++) {
            int idx = tid + i * 320;
            bkk[i] = idx / 80;
            bnn[i] = (idx % 80) * 2;
        }

        unsigned long long acc[4][8];
#pragma unroll
        for (int p = 0; p < 4; p++)
#pragma unroll
            for (int j = 0; j < 8; j++) acc[p][j] = 0ull;

        float2 Ar[4], Br[5];
#define LOADT(K0) do {                                                        \
        _Pragma("unroll")                                                     \
        for (int i = 0; i < 4; i++)                                           \
            Ar[i] = *(const float2*)(A + abase[i] + (K0) + acol[i]);          \
        _Pragma("unroll")                                                     \
        for (int i = 0; i < 5; i++) {                                         \
            int gc = col0 + bnn[i];                                           \
            Br[i] = (gc < 300)                                                \
                  ? *(const float2*)(W + (long)((K0) + bkk[i]) * 300 + gc)    \
                  : make_float2(0.f, 0.f);                                    \
        }                                                                     \
    } while (0)

        LOADT(0);
        for (int kt = 0; kt < NKT; kt++) {
            __syncthreads();
#pragma unroll
            for (int i = 0; i < 4; i++) {
                G.As[acol[i]][arow_s[i]]     = Ar[i].x;
                G.As[acol[i] + 1][arow_s[i]] = Ar[i].y;
            }
#pragma unroll
            for (int i = 0; i < 5; i++) {
                G.Bs2[bkk[i]][bnn[i]]     = pack2(Br[i].x, Br[i].x);
                G.Bs2[bkk[i]][bnn[i] + 1] = pack2(Br[i].y, Br[i].y);
            }
            __syncthreads();
            if (kt + 1 < NKT) LOADT((kt + 1) * BK);

#pragma unroll
            for (int kk = 0; kk < BK; kk++) {
                ulonglong2 a01 = *(const ulonglong2*)&G.As[kk][tr * 8];
                ulonglong2 a23 = *(const ulonglong2*)&G.As[kk][tr * 8 + 4];
                ulonglong2 b01 = *(const ulonglong2*)&G.Bs2[kk][tc * 8];
                ulonglong2 b23 = *(const ulonglong2*)&G.Bs2[kk][tc * 8 + 2];
                ulonglong2 b45 = *(const ulonglong2*)&G.Bs2[kk][tc * 8 + 4];
                ulonglong2 b67 = *(const ulonglong2*)&G.Bs2[kk][tc * 8 + 6];
                unsigned long long b[8] = {b01.x, b01.y, b23.x, b23.y,
                                           b45.x, b45.y, b67.x, b67.y};
#pragma unroll
                for (int j = 0; j < 8; j++) {
                    FMA2(acc[0][j], a01.x, b[j], acc[0][j]);
                    FMA2(acc[1][j], a01.y, b[j], acc[1][j]);
                    FMA2(acc[2][j], a23.x, b[j], acc[2][j]);
                    FMA2(acc[3][j], a23.y, b[j], acc[3][j]);
                }
            }
        }
#undef LOADT

        float bv[8];
#pragma unroll
        for (int j = 0; j < 8; j++) {
            int gc = col0 + tc * 8 + j;
            bv[j] = (gc < 300) ? bias[gc] : 0.f;
        }
#pragma unroll
        for (int p = 0; p < 4; p++) {
            int r = row0 + tr * 8 + 2 * p;
#pragma unroll
            for (int j = 0; j < 8; j++) {
                int gc = col0 + tc * 8 + j;
                if (gc < 300) {
                    float2 v = unpack2(acc[p][j]);
                    g_X[(long)r * 300 + gc]       = v.x + bv[j];
                    g_X[(long)(r + 1) * 300 + gc] = v.y + bv[j];
                }
            }
        }
        __threadfence();
        __syncthreads();
        if (tid == 0) atomicAdd(&g_flag[mchunk], 1);
        return;
    }

    // ================= LSTM consumer (blocks 0..23) =================
    LstmSmem& L = *reinterpret_cast<LstmSmem*>(smbuf);
    const int m = blockIdx.x;
    const int n = tid;                // 0..319, active < 300

    unsigned long long U2[38];
    if (n < G4) {
#pragma unroll
        for (int q = 0; q < 37; q++)
            U2[q] = pack2(U[(2 * q) * G4 + n], U[(2 * q + 1) * G4 + n]);
        U2[37] = pack2(U[74 * G4 + n], 0.0f);
    }
    if (n < 80) L.h[n] = 0.0f;
    float c = 0.0f;

    const float* xp = g_X + (long)m * G4 + n;
    int cur_chunk = -1;

    // ---- wait until all chunks <= need are produced ----
#define WAIT_CHUNKS(need_) do {                                               \
        int _need = (need_);                                                  \
        if (_need > cur_chunk) {                                              \
            if (n == 0) {                                                     \
                volatile int* f = g_flag;                                     \
                for (int ch = cur_chunk + 1; ch <= _need; ++ch)               \
                    while (f[ch] < 2) {}                                      \
            }                                                                 \
            __threadfence();                                                  \
            __syncthreads();                                                  \
            cur_chunk = _need;                                                \
        }                                                                     \
    } while (0)

    // prologue: fill PF-deep register pipeline (steps 0..PF-1)
    WAIT_CHUNKS(((PF - 1) * LSTM_B + (LSTM_B - 1)) >> 7);
    float xbuf[PF];
#pragma unroll
    for (int j = 0; j < PF; j++)
        xbuf[j] = (n < G4) ? xp[(long)j * (LSTM_B * G4)] : 0.0f;

    for (int t0 = 0; t0 < NSEQ; t0 += PF) {
        // ensure chunks for all loads issued in this block (t0+PF .. t0+2PF-1)
        int lastload = t0 + 2 * PF - 1;
        if (lastload >= NSEQ) lastload = NSEQ - 1;
        WAIT_CHUNKS((lastload * LSTM_B + (LSTM_B - 1)) >> 7);

#pragma unroll
        for (int j = 0; j < PF; j++) {
            const int t = t0 + j;

            // issue prefetch for step t+PF (consumed PF steps later)
            float xnew = 0.0f;
            if (t + PF < NSEQ && n < G4)
                xnew = xp[(long)(t + PF) * (LSTM_B * G4)];
            const float xv = xbuf[j];

            if (n < G4) {
                const ulonglong2* h2 = (const ulonglong2*)L.h;
                unsigned long long a0 = 0ull, a1 = 0ull, a2 = 0ull, a3 = 0ull;
#pragma unroll
                for (int q = 0; q < 19; q += 2) {
                    ulonglong2 hv = h2[q];
                    FMA2(a0, hv.x, U2[2 * q],     a0);
                    FMA2(a1, hv.y, U2[2 * q + 1], a1);
                }
#pragma unroll
                for (int q = 1; q < 19; q += 2) {
                    ulonglong2 hv = h2[q];
                    FMA2(a2, hv.x, U2[2 * q],     a2);
                    FMA2(a3, hv.y, U2[2 * q + 1], a3);
                }
                ADD2(a0, a0, a1);
                ADD2(a2, a2, a3);
                ADD2(a0, a0, a2);
                float2 zz = unpack2(a0);
                float z = xv + zz.x + zz.y;
                float a;
                if (n >= 150 && n < 225) a = tanhf_(z);    // g gate
                else                     a = sigmoidf_(z); // i, f, o
                L.act[n] = a;
            }
            __syncthreads();

            if (n < H_LSTM) {
                float ai = L.act[n];
                float af = L.act[75 + n];
                float ag = L.act[150 + n];
                float ao = L.act[225 + n];
                c = af * c + ai * ag;
                float h = ao * tanhf_(c);
                L.h[n] = h;
                if ((t % 18) >= 12)   // only steps ctx_kernel reads
                    g_H[(long)t * (LSTM_B * H_LSTM) + m * H_LSTM + n] = h;
            }
            __syncthreads();
            xbuf[j] = xnew;
        }
    }
#undef WAIT_CHUNKS
}

// =====================================================================
// K3: ctx (u=2 row only)
// =====================================================================
__global__ __launch_bounds__(128) void ctx_kernel(
    const float* __restrict__ Wtw,    // 75 x 300
    const float* __restrict__ btw,    // 300
    const float* __restrict__ Atw,    // 6
    const float* __restrict__ Btw,    // 1
    const float* __restrict__ in)     // inputs
{
    const int t = blockIdx.x;         // 0..255
    const int tid = threadIdx.x;

    __shared__ float mv[H_LSTM];

    if (tid < H_LSTM) {
        float acc = 0.0f;
#pragma unroll
        for (int nn = 0; nn < NT1; nn++) {
            int s = (t * 3 + 2) * 6 + nn;
            const float* hp = g_H + (long)s * (LSTM_B * H_LSTM) + tid;
            float sm = 0.0f;
#pragma unroll
            for (int mm = 0; mm < LSTM_B; mm++) sm += hp[mm * H_LSTM];
            acc += Atw[nn] * sm;
        }
        mv[tid] = acc * (1.0f / 24.0f);
    }
    __syncthreads();

    float sumA = 0.0f;
#pragma unroll
    for (int nn = 0; nn < NT1; nn++) sumA += Atw[nn];
    const float B0 = Btw[0];
    const float c1 = 1000.0f / 1001.0f;

    for (int f = tid; f < WE; f += blockDim.x) {
        float acc = 0.0f;
#pragma unroll
        for (int j = 0; j < H_LSTM; j++) acc += mv[j] * Wtw[j * WE + f];
        g_ctx[t * CTXF + f] = c1 * (acc + sumA * btw[f]) + B0;
    }
    for (int q = tid; q < TE; q += blockDim.x) {
        float acc = 0.0f;
#pragma unroll
        for (int nn = 0; nn < NT1; nn++) {
            int s = (t * 3 + 2) * 6 + nn;
            acc += Atw[nn] * in[(long)s * D_IN + SL * WE + q];
        }
        g_ctx[t * CTXF + WE + q] = acc * (1.0f / 1001.0f) + B0;
    }
}

// =====================================================================
// K4: XG[t][n] = ctx[t] . gru_W[:,n] + gru_b[0][n]
// =====================================================================
__global__ __launch_bounds__(256) void xg_kernel(
    const float* __restrict__ gruW,   // 310 x 231
    const float* __restrict__ grub)   // 2 x 231
{
    const int t = blockIdx.x;
    const int tid = threadIdx.x;
    __shared__ float xs[CTXF];
    for (int i = tid; i < CTXF; i += blockDim.x) xs[i] = g_ctx[t * CTXF + i];
    __syncthreads();
    for (int nn = tid; nn < G3; nn += blockDim.x) {
        float acc = grub[nn];
        for (int k = 0; k < CTXF; k++) acc += xs[k] * gruW[k * G3 + nn];
        g_XG[t * G3 + nn] = acc;
    }
}

// =====================================================================
// K5: GRU recurrence (single 256-step sequence), k-packed f32x2.
// =====================================================================
__global__ __launch_bounds__(256, 1) void gru_kernel(
    const float* __restrict__ gruU,   // 77 x 231
    const float* __restrict__ grub)   // 2 x 231
{
    const int n = threadIdx.x;        // 0..255 (active < 231)

    __shared__ __align__(16) float h_s[80];
    __shared__ float rg_s[G3];

    unsigned long long U2[40];
    float b1n = 0.0f;
    if (n < G3) {
#pragma unroll
        for (int q = 0; q < 38; q++)
            U2[q] = pack2(gruU[(2 * q) * G3 + n], gruU[(2 * q + 1) * G3 + n]);
        U2[38] = pack2(gruU[76 * G3 + n], 0.0f);
        U2[39] = 0ull;
        b1n = grub[G3 + n];
    }
    if (n < 80) h_s[n] = 0.0f;
    __syncthreads();

    for (int t = 0; t < BATCH; t++) {
        if (n < G3) {
            const ulonglong2* h2 = (const ulonglong2*)h_s;
            unsigned long long a0 = 0ull, a1 = 0ull, a2 = 0ull, a3 = 0ull;
#pragma unroll
            for (int q = 0; q < 20; q += 2) {
                ulonglong2 hv = h2[q];
                FMA2(a0, hv.x, U2[2 * q],     a0);
                FMA2(a1, hv.y, U2[2 * q + 1], a1);
            }
#pragma unroll
            for (int q = 1; q < 20; q += 2) {
                ulonglong2 hv = h2[q];
                FMA2(a2, hv.x, U2[2 * q],     a2);
                FMA2(a3, hv.y, U2[2 * q + 1], a3);
            }
            ADD2(a0, a0, a1);
            ADD2(a2, a2, a3);
            ADD2(a0, a0, a2);
            float2 zz = unpack2(a0);
            rg_s[n] = b1n + zz.x + zz.y;
        }
        __syncthreads();

        if (n < H_GRU) {
            float xz = g_XG[t * G3 + n];
            float xr = g_XG[t * G3 + H_GRU + n];
            float xh = g_XG[t * G3 + 2 * H_GRU + n];
            float z = sigmoidf_(xz + rg_s[n]);
            float r = sigmoidf_(xr + rg_s[H_GRU + n]);
            float hh = tanhf_(xh + r * rg_s[2 * H_GRU + n]);
            float hold = h_s[n];
            float h = z * hold + (1.0f - z) * hh;
            h_s[n] = h;
            g_seqlast[t * H_GRU + n] = h;
        }
        __syncthreads();
    }
}

// =====================================================================
// K6: logits + softmax
// =====================================================================
__global__ __launch_bounds__(32) void out_kernel(
    const float* __restrict__ linW,   // 77 x 27
    const float* __restrict__ linb,   // 27
    float* __restrict__ out)          // 256 x 27
{
    const int t = blockIdx.x;
    const int c = threadIdx.x;        // 0..31 (active < 27)

    float logit = 0.0f;
    if (c < CLS) {
        logit = linb[c];
        const float* hp = g_seqlast + t * H_GRU;
#pragma unroll
        for (int k = 0; k < H_GRU; k++) logit += hp[k] * linW[k * CLS + c];
    }

    float x = (c < CLS) ? logit : -3.4e38f;
    float mx = x;
#pragma unroll
    for (int off = 16; off > 0; off >>= 1)
        mx = fmaxf(mx, __shfl_xor_sync(0xffffffffu, mx, off));
    float e = (c < CLS) ? __expf(logit - mx) : 0.0f;
    float s = e;
#pragma unroll
    for (int off = 16; off > 0; off >>= 1)
        s += __shfl_xor_sync(0xffffffffu, s, off);
    if (c < CLS) out[t * CLS + c] = e / s;
}

// =====================================================================
extern "C" void kernel_launch(void* const* d_in, const int* in_sizes, int n_in,
                              void* d_out, int out_size)
{
    (void)in_sizes; (void)n_in; (void)out_size;
    const float* inputs   = (const float*)d_in[0];
    const float* lstm_W   = (const float*)d_in[1];
    const float* lstm_U   = (const float*)d_in[2];
    const float* lstm_b   = (const float*)d_in[3];
    const float* lin_tw_W = (const float*)d_in[4];
    const float* lin_tw_b = (const float*)d_in[5];
    const float* A_tweets = (const float*)d_in[6];
    const float* B_tweets = (const float*)d_in[7];
    const float* gru_W    = (const float*)d_in[8];
    const float* gru_U    = (const float*)d_in[9];
    const float* gru_b    = (const float*)d_in[10];
    const float* lin_W    = (const float*)d_in[11];
    const float* lin_b    = (const float*)d_in[12];
    float* out = (float*)d_out;

    init_flags_kernel<<<1, MCHUNKS>>>();
    fused_kernel<<<LSTM_B + NBLK_GEMM, 320>>>(inputs, lstm_W, lstm_b, lstm_U);
    ctx_kernel<<<256, 128>>>(lin_tw_W, lin_tw_b, A_tweets, B_tweets, inputs);
    xg_kernel<<<256, 256>>>(gru_W, gru_b);
    gru_kernel<<<1, 256>>>(gru_U, gru_b);
    out_kernel<<<256, 32>>>(lin_W, lin_b, out);
}

// round 9
// speedup vs baseline: 1.0019x; 1.0019x over previous
#include <cuda_runtime.h>
#include <math.h>

// ---------------- Problem constants ----------------
#define WE 300
#define TE 10
#define SL 24
#define NT1 6
#define UT 3
#define H_LSTM 75          // WE/4
#define H_GRU 77           // (WE+TE)/4
#define CLS 27
#define D_IN 7210          // SL*WE + TE
#define BATCH 256
#define NSEQ 4608          // LSTM scan length
#define LSTM_B 24          // independent LSTM sequences
#define G4 300             // 4*H_LSTM
#define G3 231             // 3*H_GRU
#define CTXF 310           // WE+TE

// GEMM tiling
#define BM 128
#define BN 160
#define BK 20
#define NKT 15             // 300 / 20, exact
#define MCHUNKS 864        // 110592 / 128
#define NBLK_GEMM 1728     // MCHUNKS * 2

// LSTM X-prefetch depth (register ring, unrolled)
#define PF 8               // 4608 % 8 == 0

// ---------------- Scratch ----------------
__device__ float g_X[(long)NSEQ * LSTM_B * G4];     // ~132.7 MB
__device__ float g_H[(long)NSEQ * LSTM_B * H_LSTM]; // only t%18>=12 written
__device__ float g_ctx[BATCH * CTXF];
__device__ float g_XG[BATCH * G3];
__device__ float g_seqlast[BATCH * H_GRU];
__device__ int   g_flag[MCHUNKS];                   // per-M-chunk done count (target 2)

// ---------------- f32x2 packed helpers ----------------
__device__ __forceinline__ unsigned long long pack2(float lo, float hi) {
    unsigned long long r;
    asm("mov.b64 %0, {%1, %2};" : "=l"(r) : "f"(lo), "f"(hi));
    return r;
}
__device__ __forceinline__ float2 unpack2(unsigned long long v) {
    float2 f;
    asm("mov.b64 {%0, %1}, %2;" : "=f"(f.x), "=f"(f.y) : "l"(v));
    return f;
}
#define FMA2(d, a, b, c) \
    asm("fma.rn.f32x2 %0, %1, %2, %3;" : "=l"(d) : "l"(a), "l"(b), "l"(c))
#define ADD2(d, a, b) \
    asm("add.rn.f32x2 %0, %1, %2;" : "=l"(d) : "l"(a), "l"(b))

// ---------------- Activation helpers ----------------
__device__ __forceinline__ float sigmoidf_(float x) {
    return 1.0f / (1.0f + __expf(-x));
}
__device__ __forceinline__ float tanhf_(float x) {
    float e = __expf(-2.0f * fabsf(x));
    float t = (1.0f - e) / (1.0f + e);
    return copysignf(t, x);
}

// ---------------- Flag reset (runs before fused kernel each replay) ------
__global__ void init_flags_kernel() {
    if (threadIdx.x < MCHUNKS) g_flag[threadIdx.x] = 0;
}

// ---------------- Shared-memory overlays ----------------
struct GemmSmem {
    unsigned long long Bs2[BK][BN];   // B dup'd {b,b}: 25600 B
    float As[BK][BM];                 // A transposed [k][m]: 10240 B
};
struct LstmSmem {
    float h[80];
    float act[G4];
};

// =====================================================================
// FUSED kernel: blocks 0..23 = LSTM consumers, blocks 24.. = GEMM
// producers. LSTM keeps an 8-deep register pipeline of g_X loads so
// DRAM/L2 latency (~600-1000cyc) is fully covered (~8 steps of cover).
// =====================================================================
__global__ __launch_bounds__(320, 1) void fused_kernel(
    const float* __restrict__ A,      // inputs
    const float* __restrict__ W,      // lstm_W 300x300
    const float* __restrict__ bias,   // lstm_b 300
    const float* __restrict__ U)      // lstm_U 75x300
{
    __shared__ __align__(16) char smbuf[sizeof(GemmSmem)];
    const int tid = threadIdx.x;

    if (blockIdx.x >= LSTM_B) {
        // ================= GEMM producer =================
        GemmSmem& G = *reinterpret_cast<GemmSmem*>(smbuf);
        const int g = blockIdx.x - LSTM_B;
        const int mchunk = g >> 1;
        const int row0 = mchunk * BM;
        const int col0 = (g & 1) * BN;    // 0 or 160
        const int tr = tid / 20;          // 0..15 -> 8 M rows (4 pairs)
        const int tc = tid % 20;          // 0..19 -> 8 N cols

        // A-loader: 128 rows x 10 float2 = 1280 = 4/thread
        long abase[4]; int acol[4]; int arow_s[4];
#pragma unroll
        for (int i = 0; i < 4; i++) {
            int idx = tid + i * 320;
            arow_s[i] = idx / 10;
            int r = row0 + arow_s[i];
            abase[i] = (long)r * 300 + (r / 24) * 10;  // = s*7210 + m*300
            acol[i]  = (idx % 10) * 2;
        }
        // B-loader: 20 x 80 float2 = 1600 = 5/thread
        int bkk[5], bnn[5];
#pragma unroll
        for (int i = 0; i < 5; i++) {
            int idx = tid + i * 320;
            bkk[i] = idx / 80;
            bnn[i] = (idx % 80) * 2;
        }

        unsigned long long acc[4][8];
#pragma unroll
        for (int p = 0; p < 4; p++)
#pragma unroll
            for (int j = 0; j < 8; j++) acc[p][j] = 0ull;

        float2 Ar[4], Br[5];
#define LOADT(K0) do {                                                        \
        _Pragma("unroll")                                                     \
        for (int i = 0; i < 4; i++)                                           \
            Ar[i] = *(const float2*)(A + abase[i] + (K0) + acol[i]);          \
        _Pragma("unroll")                                                     \
        for (int i = 0; i < 5; i++) {                                         \
            int gc = col0 + bnn[i];                                           \
            Br[i] = (gc < 300)                                                \
                  ? *(const float2*)(W + (long)((K0) + bkk[i]) * 300 + gc)    \
                  : make_float2(0.f, 0.f);                                    \
        }                                                                     \
    } while (0)

        LOADT(0);
        for (int kt = 0; kt < NKT; kt++) {
            __syncthreads();
#pragma unroll
            for (int i = 0; i < 4; i++) {
                G.As[acol[i]][arow_s[i]]     = Ar[i].x;
                G.As[acol[i] + 1][arow_s[i]] = Ar[i].y;
            }
#pragma unroll
            for (int i = 0; i < 5; i++) {
                G.Bs2[bkk[i]][bnn[i]]     = pack2(Br[i].x, Br[i].x);
                G.Bs2[bkk[i]][bnn[i] + 1] = pack2(Br[i].y, Br[i].y);
            }
            __syncthreads();
            if (kt + 1 < NKT) LOADT((kt + 1) * BK);

#pragma unroll
            for (int kk = 0; kk < BK; kk++) {
                ulonglong2 a01 = *(const ulonglong2*)&G.As[kk][tr * 8];
                ulonglong2 a23 = *(const ulonglong2*)&G.As[kk][tr * 8 + 4];
                ulonglong2 b01 = *(const ulonglong2*)&G.Bs2[kk][tc * 8];
                ulonglong2 b23 = *(const ulonglong2*)&G.Bs2[kk][tc * 8 + 2];
                ulonglong2 b45 = *(const ulonglong2*)&G.Bs2[kk][tc * 8 + 4];
                ulonglong2 b67 = *(const ulonglong2*)&G.Bs2[kk][tc * 8 + 6];
                unsigned long long b[8] = {b01.x, b01.y, b23.x, b23.y,
                                           b45.x, b45.y, b67.x, b67.y};
#pragma unroll
                for (int j = 0; j < 8; j++) {
                    FMA2(acc[0][j], a01.x, b[j], acc[0][j]);
                    FMA2(acc[1][j], a01.y, b[j], acc[1][j]);
                    FMA2(acc[2][j], a23.x, b[j], acc[2][j]);
                    FMA2(acc[3][j], a23.y, b[j], acc[3][j]);
                }
            }
        }
#undef LOADT

        float bv[8];
#pragma unroll
        for (int j = 0; j < 8; j++) {
            int gc = col0 + tc * 8 + j;
            bv[j] = (gc < 300) ? bias[gc] : 0.f;
        }
#pragma unroll
        for (int p = 0; p < 4; p++) {
            int r = row0 + tr * 8 + 2 * p;
#pragma unroll
            for (int j = 0; j < 8; j++) {
                int gc = col0 + tc * 8 + j;
                if (gc < 300) {
                    float2 v = unpack2(acc[p][j]);
                    g_X[(long)r * 300 + gc]       = v.x + bv[j];
                    g_X[(long)(r + 1) * 300 + gc] = v.y + bv[j];
                }
            }
        }
        __threadfence();
        __syncthreads();
        if (tid == 0) atomicAdd(&g_flag[mchunk], 1);
        return;
    }

    // ================= LSTM consumer (blocks 0..23) =================
    LstmSmem& L = *reinterpret_cast<LstmSmem*>(smbuf);
    const int m = blockIdx.x;
    const int n = tid;                // 0..319, active < 300

    unsigned long long U2[38];
    if (n < G4) {
#pragma unroll
        for (int q = 0; q < 37; q++)
            U2[q] = pack2(U[(2 * q) * G4 + n], U[(2 * q + 1) * G4 + n]);
        U2[37] = pack2(U[74 * G4 + n], 0.0f);
    }
    if (n < 80) L.h[n] = 0.0f;
    float c = 0.0f;

    const float* xp = g_X + (long)m * G4 + n;
    int cur_chunk = -1;

    // ---- wait until all chunks <= need are produced ----
#define WAIT_CHUNKS(need_) do {                                               \
        int _need = (need_);                                                  \
        if (_need > cur_chunk) {                                              \
            if (n == 0) {                                                     \
                volatile int* f = g_flag;                                     \
                for (int ch = cur_chunk + 1; ch <= _need; ++ch)               \
                    while (f[ch] < 2) {}                                      \
            }                                                                 \
            __threadfence();                                                  \
            __syncthreads();                                                  \
            cur_chunk = _need;                                                \
        }                                                                     \
    } while (0)

    // prologue: fill PF-deep register pipeline (steps 0..PF-1)
    WAIT_CHUNKS(((PF - 1) * LSTM_B + (LSTM_B - 1)) >> 7);
    float xbuf[PF];
#pragma unroll
    for (int j = 0; j < PF; j++)
        xbuf[j] = (n < G4) ? xp[(long)j * (LSTM_B * G4)] : 0.0f;

    for (int t0 = 0; t0 < NSEQ; t0 += PF) {
        // ensure chunks for all loads issued in this block (t0+PF .. t0+2PF-1)
        int lastload = t0 + 2 * PF - 1;
        if (lastload >= NSEQ) lastload = NSEQ - 1;
        WAIT_CHUNKS((lastload * LSTM_B + (LSTM_B - 1)) >> 7);

#pragma unroll
        for (int j = 0; j < PF; j++) {
            const int t = t0 + j;

            // issue prefetch for step t+PF (consumed PF steps later)
            float xnew = 0.0f;
            if (t + PF < NSEQ && n < G4)
                xnew = xp[(long)(t + PF) * (LSTM_B * G4)];
            const float xv = xbuf[j];

            if (n < G4) {
                const ulonglong2* h2 = (const ulonglong2*)L.h;
                unsigned long long a0 = 0ull, a1 = 0ull, a2 = 0ull, a3 = 0ull;
#pragma unroll
                for (int q = 0; q < 19; q += 2) {
                    ulonglong2 hv = h2[q];
                    FMA2(a0, hv.x, U2[2 * q],     a0);
                    FMA2(a1, hv.y, U2[2 * q + 1], a1);
                }
#pragma unroll
                for (int q = 1; q < 19; q += 2) {
                    ulonglong2 hv = h2[q];
                    FMA2(a2, hv.x, U2[2 * q],     a2);
                    FMA2(a3, hv.y, U2[2 * q + 1], a3);
                }
                ADD2(a0, a0, a1);
                ADD2(a2, a2, a3);
                ADD2(a0, a0, a2);
                float2 zz = unpack2(a0);
                float z = xv + zz.x + zz.y;
                float a;
                if (n >= 150 && n < 225) a = tanhf_(z);    // g gate
                else                     a = sigmoidf_(z); // i, f, o
                L.act[n] = a;
            }
            __syncthreads();

            if (n < H_LSTM) {
                float ai = L.act[n];
                float af = L.act[75 + n];
                float ag = L.act[150 + n];
                float ao = L.act[225 + n];
                c = af * c + ai * ag;
                float h = ao * tanhf_(c);
                L.h[n] = h;
                if ((t % 18) >= 12)   // only steps ctx_kernel reads
                    g_H[(long)t * (LSTM_B * H_LSTM) + m * H_LSTM + n] = h;
            }
            __syncthreads();
            xbuf[j] = xnew;
        }
    }
#undef WAIT_CHUNKS
}

// =====================================================================
// K3: ctx (u=2 row only)
// =====================================================================
__global__ __launch_bounds__(128) void ctx_kernel(
    const float* __restrict__ Wtw,    // 75 x 300
    const float* __restrict__ btw,    // 300
    const float* __restrict__ Atw,    // 6
    const float* __restrict__ Btw,    // 1
    const float* __restrict__ in)     // inputs
{
    const int t = blockIdx.x;         // 0..255
    const int tid = threadIdx.x;

    __shared__ float mv[H_LSTM];

    if (tid < H_LSTM) {
        float acc = 0.0f;
#pragma unroll
        for (int nn = 0; nn < NT1; nn++) {
            int s = (t * 3 + 2) * 6 + nn;
            const float* hp = g_H + (long)s * (LSTM_B * H_LSTM) + tid;
            float sm = 0.0f;
#pragma unroll
            for (int mm = 0; mm < LSTM_B; mm++) sm += hp[mm * H_LSTM];
            acc += Atw[nn] * sm;
        }
        mv[tid] = acc * (1.0f / 24.0f);
    }
    __syncthreads();

    float sumA = 0.0f;
#pragma unroll
    for (int nn = 0; nn < NT1; nn++) sumA += Atw[nn];
    const float B0 = Btw[0];
    const float c1 = 1000.0f / 1001.0f;

    for (int f = tid; f < WE; f += blockDim.x) {
        float acc = 0.0f;
#pragma unroll
        for (int j = 0; j < H_LSTM; j++) acc += mv[j] * Wtw[j * WE + f];
        g_ctx[t * CTXF + f] = c1 * (acc + sumA * btw[f]) + B0;
    }
    for (int q = tid; q < TE; q += blockDim.x) {
        float acc = 0.0f;
#pragma unroll
        for (int nn = 0; nn < NT1; nn++) {
            int s = (t * 3 + 2) * 6 + nn;
            acc += Atw[nn] * in[(long)s * D_IN + SL * WE + q];
        }
        g_ctx[t * CTXF + WE + q] = acc * (1.0f / 1001.0f) + B0;
    }
}

// =====================================================================
// K4: XG[t][n] = ctx[t] . gru_W[:,n] + gru_b[0][n]
// =====================================================================
__global__ __launch_bounds__(256) void xg_kernel(
    const float* __restrict__ gruW,   // 310 x 231
    const float* __restrict__ grub)   // 2 x 231
{
    const int t = blockIdx.x;
    const int tid = threadIdx.x;
    __shared__ float xs[CTXF];
    for (int i = tid; i < CTXF; i += blockDim.x) xs[i] = g_ctx[t * CTXF + i];
    __syncthreads();
    for (int nn = tid; nn < G3; nn += blockDim.x) {
        float acc = grub[nn];
        for (int k = 0; k < CTXF; k++) acc += xs[k] * gruW[k * G3 + nn];
        g_XG[t * G3 + nn] = acc;
    }
}

// =====================================================================
// K5: GRU recurrence (single 256-step sequence), k-packed f32x2.
// =====================================================================
__global__ __launch_bounds__(256, 1) void gru_kernel(
    const float* __restrict__ gruU,   // 77 x 231
    const float* __restrict__ grub)   // 2 x 231
{
    const int n = threadIdx.x;        // 0..255 (active < 231)

    __shared__ __align__(16) float h_s[80];
    __shared__ float rg_s[G3];

    unsigned long long U2[40];
    float b1n = 0.0f;
    if (n < G3) {
#pragma unroll
        for (int q = 0; q < 38; q++)
            U2[q] = pack2(gruU[(2 * q) * G3 + n], gruU[(2 * q + 1) * G3 + n]);
        U2[38] = pack2(gruU[76 * G3 + n], 0.0f);
        U2[39] = 0ull;
        b1n = grub[G3 + n];
    }
    if (n < 80) h_s[n] = 0.0f;
    __syncthreads();

    for (int t = 0; t < BATCH; t++) {
        if (n < G3) {
            const ulonglong2* h2 = (const ulonglong2*)h_s;
            unsigned long long a0 = 0ull, a1 = 0ull, a2 = 0ull, a3 = 0ull;
#pragma unroll
            for (int q = 0; q < 20; q += 2) {
                ulonglong2 hv = h2[q];
                FMA2(a0, hv.x, U2[2 * q],     a0);
                FMA2(a1, hv.y, U2[2 * q + 1], a1);
            }
#pragma unroll
            for (int q = 1; q < 20; q += 2) {
                ulonglong2 hv = h2[q];
                FMA2(a2, hv.x, U2[2 * q],     a2);
                FMA2(a3, hv.y, U2[2 * q + 1], a3);
            }
            ADD2(a0, a0, a1);
            ADD2(a2, a2, a3);
            ADD2(a0, a0, a2);
            float2 zz = unpack2(a0);
            rg_s[n] = b1n + zz.x + zz.y;
        }
        __syncthreads();

        if (n < H_GRU) {
            float xz = g_XG[t * G3 + n];
            float xr = g_XG[t * G3 + H_GRU + n];
            float xh = g_XG[t * G3 + 2 * H_GRU + n];
            float z = sigmoidf_(xz + rg_s[n]);
            float r = sigmoidf_(xr + rg_s[H_GRU + n]);
            float hh = tanhf_(xh + r * rg_s[2 * H_GRU + n]);
            float hold = h_s[n];
            float h = z * hold + (1.0f - z) * hh;
            h_s[n] = h;
            g_seqlast[t * H_GRU + n] = h;
        }
        __syncthreads();
    }
}

// =====================================================================
// K6: logits + softmax
// =====================================================================
__global__ __launch_bounds__(32) void out_kernel(
    const float* __restrict__ linW,   // 77 x 27
    const float* __restrict__ linb,   // 27
    float* __restrict__ out)          // 256 x 27
{
    const int t = blockIdx.x;
    const int c = threadIdx.x;        // 0..31 (active < 27)

    float logit = 0.0f;
    if (c < CLS) {
        logit = linb[c];
        const float* hp = g_seqlast + t * H_GRU;
#pragma unroll
        for (int k = 0; k < H_GRU; k++) logit += hp[k] * linW[k * CLS + c];
    }

    float x = (c < CLS) ? logit : -3.4e38f;
    float mx = x;
#pragma unroll
    for (int off = 16; off > 0; off >>= 1)
        mx = fmaxf(mx, __shfl_xor_sync(0xffffffffu, mx, off));
    float e = (c < CLS) ? __expf(logit - mx) : 0.0f;
    float s = e;
#pragma unroll
    for (int off = 16; off > 0; off >>= 1)
        s += __shfl_xor_sync(0xffffffffu, s, off);
    if (c < CLS) out[t * CLS + c] = e / s;
}

// =====================================================================
extern "C" void kernel_launch(void* const* d_in, const int* in_sizes, int n_in,
                              void* d_out, int out_size)
{
    (void)in_sizes; (void)n_in; (void)out_size;
    const float* inputs   = (const float*)d_in[0];
    const float* lstm_W   = (const float*)d_in[1];
    const float* lstm_U   = (const float*)d_in[2];
    const float* lstm_b   = (const float*)d_in[3];
    const float* lin_tw_W = (const float*)d_in[4];
    const float* lin_tw_b = (const float*)d_in[5];
    const float* A_tweets = (const float*)d_in[6];
    const float* B_tweets = (const float*)d_in[7];
    const float* gru_W    = (const float*)d_in[8];
    const float* gru_U    = (const float*)d_in[9];
    const float* gru_b    = (const float*)d_in[10];
    const float* lin_W    = (const float*)d_in[11];
    const float* lin_b    = (const float*)d_in[12];
    float* out = (float*)d_out;

    init_flags_kernel<<<1, MCHUNKS>>>();
    fused_kernel<<<LSTM_B + NBLK_GEMM, 320>>>(inputs, lstm_W, lstm_b, lstm_U);
    ctx_kernel<<<256, 128>>>(lin_tw_W, lin_tw_b, A_tweets, B_tweets, inputs);
    xg_kernel<<<256, 256>>>(gru_W, gru_b);
    gru_kernel<<<1, 256>>>(gru_U, gru_b);
    out_kernel<<<256, 32>>>(lin_W, lin_b, out);
}